// round 15
// baseline (speedup 1.0000x reference)
#include <cuda_runtime.h>
#include <cuda_fp16.h>
#include <cstdint>

// Problem constants
#define B_    4
#define NPM_  200
#define NVM_  1500
#define D_    512
#define H_    8
#define DFF_  2048
#define NL_   3
#define S_    1702           // NPM + NVM + 2
#define M_    (B_ * S_)      // 6808 rows
#define DH_   64
#define RELW_ (NPM_ + NVM_)  // 1700

// ----------------------------------------------------------------------------
// Scratch (static device globals; no allocation allowed)
// ----------------------------------------------------------------------------
__device__ float  g_x  [M_ * D_];       // residual stream (fp32)
__device__ __half g_h  [M_ * D_];       // layernorm output (GEMM A operand)
__device__ float  g_qkv[M_ * 3 * D_];   // qkv projection (fp32, attention reads)
__device__ __half g_o  [M_ * D_];       // attention output (GEMM A operand)
__device__ __half g_ff [M_ * DFF_];     // ffn hidden (GEMM A operand)
// transposed + fp16 weights, [N][K] per layer
__device__ __half g_wqkv[NL_ * D_ * 3 * D_];
__device__ __half g_wo  [NL_ * D_ * D_];
__device__ __half g_w1  [NL_ * D_ * DFF_];
__device__ __half g_w2  [NL_ * DFF_ * D_];
// attention sparsity structure
__device__ int g_sidx[B_ * RELW_];
__device__ int g_goff[B_ * (NPM_ + 1)];

// ----------------------------------------------------------------------------
// Setup mega-kernel: weight transpose+fp16, build_x, rel counting sort.
// ----------------------------------------------------------------------------
#define TILES_PER_LAYER 3072
#define PREP_BLOCKS (NL_ * TILES_PER_LAYER)                  // 9216
#define BX_BLOCKS   ((M_ * D_ + 255) / 256)                  // 13616
#define SETUP_BLOCKS (PREP_BLOCKS + BX_BLOCKS + B_)

__global__ void setup_kernel(const float* __restrict__ Wqkv, __half* __restrict__ wqkv,
                             const float* __restrict__ Wo,   __half* __restrict__ wo,
                             const float* __restrict__ W1,   __half* __restrict__ w1,
                             const float* __restrict__ W2,   __half* __restrict__ w2,
                             const float* __restrict__ vm,
                             const float* __restrict__ ns,
                             const float* __restrict__ pm,
                             const float* __restrict__ pmW, const float* __restrict__ pmb,
                             const float* __restrict__ vmW, const float* __restrict__ vmb,
                             float* __restrict__ x,
                             const int* __restrict__ rel, int* __restrict__ sidx,
                             int* __restrict__ goff)
{
    int bx = blockIdx.x;
    int tid = threadIdx.x;

    if (bx < PREP_BLOCKS) {
        __shared__ float t[32][33];
        int layer = bx / TILES_PER_LAYER;
        int tt = bx - layer * TILES_PER_LAYER;
        const float* W; __half* Wt; int K, N, t0;
        if (tt < 768)        { W = Wqkv + (size_t)layer * D_ * 3 * D_; Wt = wqkv + (size_t)layer * D_ * 3 * D_; K = D_;   N = 3 * D_; t0 = tt; }
        else if (tt < 1024)  { W = Wo   + (size_t)layer * D_ * D_;     Wt = wo   + (size_t)layer * D_ * D_;     K = D_;   N = D_;     t0 = tt - 768; }
        else if (tt < 2048)  { W = W1   + (size_t)layer * D_ * DFF_;   Wt = w1   + (size_t)layer * D_ * DFF_;   K = D_;   N = DFF_;   t0 = tt - 1024; }
        else                 { W = W2   + (size_t)layer * DFF_ * D_;   Wt = w2   + (size_t)layer * DFF_ * D_;   K = DFF_; N = D_;     t0 = tt - 2048; }
        int ntx = N >> 5;
        int n0 = (t0 % ntx) * 32;
        int k0 = (t0 / ntx) * 32;
        int tx = tid & 31, ty = tid >> 5;
        #pragma unroll
        for (int r = ty; r < 32; r += 8)
            t[r][tx] = W[(size_t)(k0 + r) * N + n0 + tx];
        __syncthreads();
        #pragma unroll
        for (int r = ty; r < 32; r += 8)
            Wt[(size_t)(n0 + r) * K + k0 + tx] = __float2half_rn(t[tx][r]);
    } else if (bx < PREP_BLOCKS + BX_BLOCKS) {
        int idx = (bx - PREP_BLOCKS) * 256 + tid;
        if (idx >= M_ * D_) return;
        int d = idx & (D_ - 1);
        int sb = idx >> 9;
        int s = sb % S_;
        int b = sb / S_;
        float val;
        if (s == 0) {
            val = ns[b];
        } else if (s <= NPM_) {
            const float* st = pm + ((size_t)b * NPM_ + (s - 1)) * 16;
            val = pmb[d];
            #pragma unroll
            for (int c = 0; c < 16; c++) val += st[c] * pmW[c * D_ + d];
        } else if (s < S_ - 1) {
            const float* st = vm + ((size_t)b * NVM_ + (s - 1 - NPM_)) * 16;
            val = vmb[d];
            #pragma unroll
            for (int c = 0; c < 16; c++) val += st[c] * vmW[c * D_ + d];
        } else {
            val = -1.0f;
        }
        x[idx] = val;
    } else {
        __shared__ int hist[NPM_];
        __shared__ int offs[NPM_ + 1];
        __shared__ int relv[RELW_];
        int b = bx - PREP_BLOCKS - BX_BLOCKS;
        for (int i = tid; i < NPM_; i += 256) hist[i] = 0;
        __syncthreads();
        for (int i = tid; i < RELW_; i += 256) {
            int r = rel[b * RELW_ + i];
            relv[i] = r;
            atomicAdd(&hist[r], 1);
        }
        __syncthreads();
        if (tid == 0) {
            int acc = 0;
            #pragma unroll 4
            for (int r = 0; r < NPM_; r++) {
                offs[r] = acc;
                goff[b * (NPM_ + 1) + r] = acc;
                acc += hist[r];
            }
            offs[NPM_] = acc;
            goff[b * (NPM_ + 1) + NPM_] = acc;
        }
        __syncthreads();
        int* out = sidx + b * RELW_;
        for (int r = tid; r < NPM_; r += 256) {
            int o = offs[r];
            for (int p = 0; p < RELW_; p++)
                if (relv[p] == r) out[o++] = p + 1;
        }
    }
}

// ----------------------------------------------------------------------------
// LayerNorm: one warp per row of 512; output fp16 (GEMM A operand)
// ----------------------------------------------------------------------------
__global__ void ln_kernel(const float* __restrict__ x, __half* __restrict__ out,
                          const float* __restrict__ gs, const float* __restrict__ gb,
                          int M)
{
    int warp = (blockIdx.x * blockDim.x + threadIdx.x) >> 5;
    int lane = threadIdx.x & 31;
    if (warp >= M) return;
    const float* row = x + (size_t)warp * D_;
    float4 v[4];
    float sum = 0.f, sq = 0.f;
    #pragma unroll
    for (int j = 0; j < 4; j++) {
        v[j] = *reinterpret_cast<const float4*>(row + (lane + 32 * j) * 4);
        sum += v[j].x + v[j].y + v[j].z + v[j].w;
        sq  += v[j].x * v[j].x + v[j].y * v[j].y + v[j].z * v[j].z + v[j].w * v[j].w;
    }
    #pragma unroll
    for (int o = 16; o; o >>= 1) {
        sum += __shfl_xor_sync(0xffffffffu, sum, o);
        sq  += __shfl_xor_sync(0xffffffffu, sq,  o);
    }
    const float inv = 1.0f / (float)D_;
    float mean = sum * inv;
    float var  = sq * inv - mean * mean;
    float rstd = rsqrtf(var + 1e-5f);
    __half* orow = out + (size_t)warp * D_;
    #pragma unroll
    for (int j = 0; j < 4; j++) {
        int c = (lane + 32 * j) * 4;
        __half2 lo = __floats2half2_rn((v[j].x - mean) * rstd * gs[c + 0] + gb[c + 0],
                                       (v[j].y - mean) * rstd * gs[c + 1] + gb[c + 1]);
        __half2 hi = __floats2half2_rn((v[j].z - mean) * rstd * gs[c + 2] + gb[c + 2],
                                       (v[j].w - mean) * rstd * gs[c + 3] + gb[c + 3]);
        *reinterpret_cast<__half2*>(orow + c)     = lo;
        *reinterpret_cast<__half2*>(orow + c + 2) = hi;
    }
}

// ----------------------------------------------------------------------------
// fp16 tensor-core GEMM (R11 config, best measured).
// ----------------------------------------------------------------------------
#define MMA_F16(d, a, b)                                                         \
    asm volatile(                                                                \
        "mma.sync.aligned.m16n8k16.row.col.f32.f16.f16.f32 "                     \
        "{%0,%1,%2,%3}, {%4,%5,%6,%7}, {%8,%9}, {%0,%1,%2,%3};"                  \
        : "+f"((d)[0]), "+f"((d)[1]), "+f"((d)[2]), "+f"((d)[3])                 \
        : "r"((a)[0]), "r"((a)[1]), "r"((a)[2]), "r"((a)[3]),                    \
          "r"((b)[0]), "r"((b)[1]))

#define LDSM4(r0, r1, r2, r3, addr)                                              \
    asm volatile("ldmatrix.sync.aligned.m8n8.x4.shared.b16 {%0,%1,%2,%3}, [%4];" \
        : "=r"(r0), "=r"(r1), "=r"(r2), "=r"(r3) : "r"(addr))

#define HG_STAGE_BYTES 20480
#define HG_SMEM (3 * HG_STAGE_BYTES)

template<int EPI>
__global__ void __launch_bounds__(128) hgemm_kernel(
    const __half* __restrict__ A, const __half* __restrict__ Wt,
    const float* __restrict__ bias, void* __restrict__ Cv,
    int M, int N, int K)
{
    extern __shared__ char sm_[];
    const uint32_t sbase = (uint32_t)__cvta_generic_to_shared(sm_);

    const int tid  = threadIdx.x;
    const int lane = tid & 31;
    const int wid  = tid >> 5;
    const int wm   = wid >> 1;
    const int wn   = wid & 1;
    const int g    = lane >> 2;
    const int c    = lane & 3;
    const int row0 = blockIdx.y * 128;
    const int col0 = blockIdx.x * 128;
    const int nk   = K >> 5;

    float acc[4][8][4];
    #pragma unroll
    for (int i = 0; i < 4; i++)
        #pragma unroll
        for (int j = 0; j < 8; j++)
            #pragma unroll
            for (int t = 0; t < 4; t++) acc[i][j][t] = 0.f;

    auto issue = [&](int kt, int st) {
        const int k0 = kt << 5;
        const uint32_t ab = sbase + st * HG_STAGE_BYTES;
        const uint32_t bb = ab + 10240;
        #pragma unroll
        for (int i = 0; i < 4; i++) {
            int idx = tid + i * 128;
            int r = idx >> 2, q = idx & 3;
            int m = row0 + r;
            const __half* src = A + (size_t)(m < M ? m : M - 1) * K + k0 + q * 8;
            uint32_t dst = ab + r * 80 + q * 16;
            int sz = (m < M) ? 16 : 0;
            asm volatile("cp.async.ca.shared.global [%0], [%1], 16, %2;"
                         :: "r"(dst), "l"(src), "r"(sz));
        }
        #pragma unroll
        for (int i = 0; i < 4; i++) {
            int idx = tid + i * 128;
            int r = idx >> 2, q = idx & 3;
            const __half* src = Wt + (size_t)(col0 + r) * K + k0 + q * 8;
            uint32_t dst = bb + r * 80 + q * 16;
            asm volatile("cp.async.cg.shared.global [%0], [%1], 16;"
                         :: "r"(dst), "l"(src));
        }
        asm volatile("cp.async.commit_group;");
    };

    const uint32_t rowA = (uint32_t)(lane & 15);
    const uint32_t colA = (uint32_t)((lane >> 4) * 8);
    const uint32_t rowB = (uint32_t)((lane & 7) + ((lane >> 4) * 8));
    const uint32_t colB = (uint32_t)(((lane >> 3) & 1) * 8);

    issue(0, 0);
    issue(1, 1);

    for (int kt = 0; kt < nk; kt++) {
        const int st = kt % 3;
        if (kt + 1 < nk) asm volatile("cp.async.wait_group 1;");
        else             asm volatile("cp.async.wait_group 0;");
        __syncthreads();
        if (kt + 2 < nk) issue(kt + 2, (kt + 2) % 3);

        const uint32_t ab = sbase + st * HG_STAGE_BYTES;
        const uint32_t bb = ab + 10240;

        #pragma unroll
        for (int ks = 0; ks < 2; ks++) {
            const uint32_t aoff = ab + (wm * 64 + rowA) * 80 + (colA + ks * 16) * 2;
            const uint32_t boff = bb + (wn * 64 + rowB) * 80 + (colB + ks * 16) * 2;
            uint32_t bf[8][2], af[4][4];
            #pragma unroll
            for (int p = 0; p < 4; p++) {
                LDSM4(bf[2 * p][0], bf[2 * p][1], bf[2 * p + 1][0], bf[2 * p + 1][1],
                      boff + p * 16 * 80);
            }
            #pragma unroll
            for (int fm = 0; fm < 4; fm++) {
                LDSM4(af[fm][0], af[fm][1], af[fm][2], af[fm][3],
                      aoff + fm * 16 * 80);
            }
            #pragma unroll
            for (int fm = 0; fm < 4; fm++)
                #pragma unroll
                for (int fn = 0; fn < 8; fn++)
                    MMA_F16(acc[fm][fn], af[fm], bf[fn]);
        }
        __syncthreads();
    }

    const int cc = c * 2;
    #pragma unroll
    for (int fm = 0; fm < 4; fm++) {
        int mA = row0 + wm * 64 + fm * 16 + g;
        int mB = mA + 8;
        #pragma unroll
        for (int fn = 0; fn < 8; fn++) {
            int n = col0 + wn * 64 + fn * 8 + cc;
            float2 b2 = *reinterpret_cast<const float2*>(bias + n);
            float v0 = acc[fm][fn][0] + b2.x;
            float v1 = acc[fm][fn][1] + b2.y;
            float v2 = acc[fm][fn][2] + b2.x;
            float v3 = acc[fm][fn][3] + b2.y;
            if (EPI == 0) {
                float* C = (float*)Cv;
                if (mA < M) *reinterpret_cast<float2*>(C + (size_t)mA * N + n) = make_float2(v0, v1);
                if (mB < M) *reinterpret_cast<float2*>(C + (size_t)mB * N + n) = make_float2(v2, v3);
            } else if (EPI == 1) {
                float* C = (float*)Cv;
                if (mA < M) {
                    float2* p = reinterpret_cast<float2*>(C + (size_t)mA * N + n);
                    float2 o = *p; o.x += v0; o.y += v1; *p = o;
                }
                if (mB < M) {
                    float2* p = reinterpret_cast<float2*>(C + (size_t)mB * N + n);
                    float2 o = *p; o.x += v2; o.y += v3; *p = o;
                }
            } else {
                __half* C = (__half*)Cv;
                float g0 = 0.5f * v0 * (1.0f + erff(v0 * 0.70710678118654752f));
                float g1 = 0.5f * v1 * (1.0f + erff(v1 * 0.70710678118654752f));
                float g2 = 0.5f * v2 * (1.0f + erff(v2 * 0.70710678118654752f));
                float g3 = 0.5f * v3 * (1.0f + erff(v3 * 0.70710678118654752f));
                if (mA < M) *reinterpret_cast<__half2*>(C + (size_t)mA * N + n) = __floats2half2_rn(g0, g1);
                if (mB < M) *reinterpret_cast<__half2*>(C + (size_t)mB * N + n) = __floats2half2_rn(g2, g3);
            }
        }
    }
}

// ----------------------------------------------------------------------------
// Attention v4: warp per (b, query), 8 heads in lane quads, register
// double-buffered key pipeline (next key's K/V loads in flight during the
// current key's softmax math).
// Blocks [0, 850): sparse path. Blocks [850, 914): dense rows q in {0, S-1}.
// ----------------------------------------------------------------------------
#define GRP_BLOCKS2 ((B_ * RELW_) / 8)   // 850

__global__ void __launch_bounds__(256) attn_kernel(
    const float* __restrict__ qkv,
    const int* __restrict__ rel,
    const int* __restrict__ sidx,
    const int* __restrict__ goff,
    const unsigned char* __restrict__ padm,
    __half* __restrict__ obuf)
{
    __shared__ float dsm[8], dsl[8], dso[8][64];
    const size_t rs = 3 * D_;
    const int lane = threadIdx.x & 31;

    if (blockIdx.x < GRP_BLOCKS2) {
        // ---- sparse: warp per (b, query), quad-per-head, pipelined keys ----
        int gw = blockIdx.x * 8 + (threadIdx.x >> 5);   // 0..6799
        int qi = gw % RELW_;
        int b  = gw / RELW_;
        int qpos = 1 + qi;

        const float* bb = qkv + (size_t)b * S_ * rs;
        const float* qrow = bb + (size_t)qpos * rs + lane * 16;
        float4 q[4];
        #pragma unroll
        for (int c = 0; c < 4; c++) q[c] = *reinterpret_cast<const float4*>(qrow + c * 4);

        int r   = rel[b * RELW_ + qi];
        int it  = goff[b * (NPM_ + 1) + r];
        const int end = goff[b * (NPM_ + 1) + r + 1];
        const int* glist = sidx + b * RELW_;

        // filtered virtual key stream: 0, S-1, then non-padded group members
        int phase = 0;
        auto fetch_next = [&]() -> int {
            if (phase == 0) { phase = 1; return 0; }
            if (phase == 1) { phase = 2; return S_ - 1; }
            while (it < end) {
                int kp = glist[it++];
                if (kp > NPM_ && padm[b * NVM_ + kp - 1 - NPM_]) continue;
                return kp;
            }
            return -1;
        };

        float m = -1e30f, l = 0.f;
        float4 o[4];
        #pragma unroll
        for (int c = 0; c < 4; c++) o[c] = make_float4(0.f, 0.f, 0.f, 0.f);

        float4 kkA[4], vvA[4], kkB[4], vvB[4];

        auto loadA = [&](int kpos) {
            const float* kr = bb + (size_t)kpos * rs + D_ + lane * 16;
            const float* vr = kr + D_;
            #pragma unroll
            for (int c = 0; c < 4; c++) kkA[c] = *reinterpret_cast<const float4*>(kr + c * 4);
            #pragma unroll
            for (int c = 0; c < 4; c++) vvA[c] = *reinterpret_cast<const float4*>(vr + c * 4);
        };
        auto loadB = [&](int kpos) {
            const float* kr = bb + (size_t)kpos * rs + D_ + lane * 16;
            const float* vr = kr + D_;
            #pragma unroll
            for (int c = 0; c < 4; c++) kkB[c] = *reinterpret_cast<const float4*>(kr + c * 4);
            #pragma unroll
            for (int c = 0; c < 4; c++) vvB[c] = *reinterpret_cast<const float4*>(vr + c * 4);
        };
        auto procA = [&]() {
            float p = 0.f;
            #pragma unroll
            for (int c = 0; c < 4; c++)
                p += q[c].x * kkA[c].x + q[c].y * kkA[c].y + q[c].z * kkA[c].z + q[c].w * kkA[c].w;
            p += __shfl_xor_sync(0xffffffffu, p, 1);
            p += __shfl_xor_sync(0xffffffffu, p, 2);
            float s = p * 0.125f;
            float mn = fmaxf(m, s);
            float corr = __expf(m - mn);
            float e    = __expf(s - mn);
            #pragma unroll
            for (int c = 0; c < 4; c++) {
                o[c].x = o[c].x * corr + e * vvA[c].x;
                o[c].y = o[c].y * corr + e * vvA[c].y;
                o[c].z = o[c].z * corr + e * vvA[c].z;
                o[c].w = o[c].w * corr + e * vvA[c].w;
            }
            l = l * corr + e;
            m = mn;
        };
        auto procB = [&]() {
            float p = 0.f;
            #pragma unroll
            for (int c = 0; c < 4; c++)
                p += q[c].x * kkB[c].x + q[c].y * kkB[c].y + q[c].z * kkB[c].z + q[c].w * kkB[c].w;
            p += __shfl_xor_sync(0xffffffffu, p, 1);
            p += __shfl_xor_sync(0xffffffffu, p, 2);
            float s = p * 0.125f;
            float mn = fmaxf(m, s);
            float corr = __expf(m - mn);
            float e    = __expf(s - mn);
            #pragma unroll
            for (int c = 0; c < 4; c++) {
                o[c].x = o[c].x * corr + e * vvB[c].x;
                o[c].y = o[c].y * corr + e * vvB[c].y;
                o[c].z = o[c].z * corr + e * vvB[c].z;
                o[c].w = o[c].w * corr + e * vvB[c].w;
            }
            l = l * corr + e;
            m = mn;
        };

        // pipelined main loop (first key always exists: position 0)
        int ka = fetch_next();
        loadA(ka);
        int kb = fetch_next();
        for (;;) {
            if (kb >= 0) loadB(kb);
            procA();
            if (kb < 0) break;
            int kc = fetch_next();
            if (kc >= 0) loadA(kc);
            procB();
            if (kc < 0) break;
            kb = fetch_next();
        }

        float inv = 1.0f / l;
        __half* dst = obuf + ((size_t)b * S_ + qpos) * D_ + lane * 16;
        #pragma unroll
        for (int c = 0; c < 4; c++) {
            *reinterpret_cast<__half2*>(dst + c * 4)     = __floats2half2_rn(o[c].x * inv, o[c].y * inv);
            *reinterpret_cast<__half2*>(dst + c * 4 + 2) = __floats2half2_rn(o[c].z * inv, o[c].w * inv);
        }
    } else {
        // ---- dense rows: q in {0, S-1} ----
        int bx = blockIdx.x - GRP_BLOCKS2;
        int qsel = bx & 1;
        int h = (bx >> 1) & (H_ - 1);
        int b = bx >> 4;
        int qpos = qsel ? (S_ - 1) : 0;
        int warp = threadIdx.x >> 5;

        const float* base = qkv + (size_t)b * S_ * rs + h * DH_;
        const float* qrow = base + (size_t)qpos * rs;
        float q0 = qrow[lane], q1 = qrow[lane + 32];

        float m = -1e30f, l = 0.f, o0 = 0.f, o1 = 0.f;
        for (int k = warp; k < S_; k += 8) {
            if (k > NPM_ && k < S_ - 1 && padm[b * NVM_ + k - 1 - NPM_]) continue;
            const float* krow = base + (size_t)k * rs + D_;
            float p = q0 * krow[lane] + q1 * krow[lane + 32];
            #pragma unroll
            for (int o = 16; o; o >>= 1) p += __shfl_xor_sync(0xffffffffu, p, o);
            float s = p * 0.125f;
            float mn = fmaxf(m, s);
            float corr = __expf(m - mn);
            float pe   = __expf(s - mn);
            const float* vrow = krow + D_;
            o0 = o0 * corr + pe * vrow[lane];
            o1 = o1 * corr + pe * vrow[lane + 32];
            l  = l * corr + pe;
            m  = mn;
        }
        if (lane == 0) { dsm[warp] = m; dsl[warp] = l; }
        dso[warp][lane]      = o0;
        dso[warp][lane + 32] = o1;
        __syncthreads();

        if (threadIdx.x < 64) {
            float M = -1e30f;
            #pragma unroll
            for (int w = 0; w < 8; w++) M = fmaxf(M, dsm[w]);
            float L = 0.f, ov = 0.f;
            #pragma unroll
            for (int w = 0; w < 8; w++) {
                float e = __expf(dsm[w] - M);
                L  += dsl[w] * e;
                ov += dso[w][threadIdx.x] * e;
            }
            __half* dst = obuf + ((size_t)b * S_ + qpos) * D_ + h * DH_;
            dst[threadIdx.x] = __float2half_rn(ov / L);
        }
    }
}

// ----------------------------------------------------------------------------
// Output heads
// ----------------------------------------------------------------------------
__global__ void out_kernel(const float* __restrict__ x,
                           const float* __restrict__ outW, const float* __restrict__ outb,
                           const float* __restrict__ crW,  const float* __restrict__ crb,
                           float* __restrict__ out)
{
    int warp = (blockIdx.x * blockDim.x + threadIdx.x) >> 5;
    int lane = threadIdx.x & 31;
    const int nscore = B_ * NVM_;
    if (warp >= nscore + B_) return;
    int b, s;
    const float* w;
    float bias;
    float* dst;
    if (warp < nscore) {
        b = warp / NVM_;
        s = 1 + NPM_ + (warp % NVM_);
        w = outW; bias = outb[0];
        dst = out + warp;
    } else {
        b = warp - nscore;
        s = S_ - 1;
        w = crW; bias = crb[0];
        dst = out + nscore + b;
    }
    const float* row = x + ((size_t)b * S_ + s) * D_;
    float sum = 0.f;
    for (int c = lane; c < D_; c += 32) sum += row[c] * w[c];
    #pragma unroll
    for (int o = 16; o; o >>= 1) sum += __shfl_xor_sync(0xffffffffu, sum, o);
    if (lane == 0) *dst = sum + bias;
}

// ----------------------------------------------------------------------------
// Host launcher. Launch order: setup(0), ln(1), qkv(2), attn(3 <- PROFILED).
// ----------------------------------------------------------------------------
extern "C" void kernel_launch(void* const* d_in, const int* in_sizes, int n_in,
                              void* d_out, int out_size)
{
    const float* vm   = (const float*)d_in[0];
    const float* ns   = (const float*)d_in[1];
    const float* pm   = (const float*)d_in[2];
    const int*   rel  = (const int*)  d_in[3];
    const unsigned char* padm = (const unsigned char*)d_in[4];
    const float* pmW  = (const float*)d_in[5];
    const float* pmb  = (const float*)d_in[6];
    const float* vmW  = (const float*)d_in[7];
    const float* vmb  = (const float*)d_in[8];
    const float* ln1s = (const float*)d_in[9];
    const float* ln1b = (const float*)d_in[10];
    const float* Wqkv = (const float*)d_in[11];
    const float* bqkv = (const float*)d_in[12];
    const float* Wo   = (const float*)d_in[13];
    const float* bo   = (const float*)d_in[14];
    const float* ln2s = (const float*)d_in[15];
    const float* ln2b = (const float*)d_in[16];
    const float* W1   = (const float*)d_in[17];
    const float* b1   = (const float*)d_in[18];
    const float* W2   = (const float*)d_in[19];
    const float* b2   = (const float*)d_in[20];
    const float* outW = (const float*)d_in[21];
    const float* outb = (const float*)d_in[22];
    const float* crW  = (const float*)d_in[23];
    const float* crb  = (const float*)d_in[24];

    float *x, *qkvb;
    __half *h, *ob, *ff, *wqkv, *wo, *w1, *w2;
    int *sidx, *goff;
    cudaGetSymbolAddress((void**)&x,    g_x);
    cudaGetSymbolAddress((void**)&h,    g_h);
    cudaGetSymbolAddress((void**)&qkvb, g_qkv);
    cudaGetSymbolAddress((void**)&ob,   g_o);
    cudaGetSymbolAddress((void**)&ff,   g_ff);
    cudaGetSymbolAddress((void**)&wqkv, g_wqkv);
    cudaGetSymbolAddress((void**)&wo,   g_wo);
    cudaGetSymbolAddress((void**)&w1,   g_w1);
    cudaGetSymbolAddress((void**)&w2,   g_w2);
    cudaGetSymbolAddress((void**)&sidx, g_sidx);
    cudaGetSymbolAddress((void**)&goff, g_goff);

    cudaFuncSetAttribute(hgemm_kernel<0>, cudaFuncAttributeMaxDynamicSharedMemorySize, HG_SMEM);
    cudaFuncSetAttribute(hgemm_kernel<1>, cudaFuncAttributeMaxDynamicSharedMemorySize, HG_SMEM);
    cudaFuncSetAttribute(hgemm_kernel<2>, cudaFuncAttributeMaxDynamicSharedMemorySize, HG_SMEM);

    const int lnBlocks = (M_ * 32 + 255) / 256;
    const int MB = (M_ + 127) / 128;               // 54
    const dim3 gQKV(3 * D_ / 128, MB);             // (12, 54)
    const dim3 gWO (D_ / 128,     MB);             // (4, 54)
    const dim3 gW1 (DFF_ / 128,   MB);             // (16, 54)
    const dim3 gW2 (D_ / 128,     MB);             // (4, 54)
    const int attnBlocks = GRP_BLOCKS2 + B_ * H_ * 2;  // 850 + 64

    // launch 0: setup (weight prep + build_x + sort)
    setup_kernel<<<SETUP_BLOCKS, 256>>>(Wqkv, wqkv, Wo, wo, W1, w1, W2, w2,
                                        vm, ns, pm, pmW, pmb, vmW, vmb, x,
                                        rel, sidx, goff);
    // launch 1: LN1 (layer 0)
    ln_kernel<<<lnBlocks, 256>>>(x, h, ln1s, ln1b, M_);
    // launch 2: QKV GEMM (layer 0)
    hgemm_kernel<0><<<gQKV, 128, HG_SMEM>>>(h, wqkv, bqkv, qkvb, M_, 3 * D_, D_);

    for (int i = 0; i < NL_; i++) {
        if (i > 0) {
            ln_kernel<<<lnBlocks, 256>>>(x, h, ln1s + i * D_, ln1b + i * D_, M_);
            hgemm_kernel<0><<<gQKV, 128, HG_SMEM>>>(h, wqkv + (size_t)i * D_ * 3 * D_,
                                                    bqkv + i * 3 * D_, qkvb, M_, 3 * D_, D_);
        }
        // layer 0 attn is launch index 3 -> PROFILED
        attn_kernel<<<attnBlocks, 256>>>(qkvb, rel, sidx, goff, padm, ob);
        hgemm_kernel<1><<<gWO, 128, HG_SMEM>>>(ob, wo + (size_t)i * D_ * D_,
                                               bo + i * D_, x, M_, D_, D_);
        ln_kernel<<<lnBlocks, 256>>>(x, h, ln2s + i * D_, ln2b + i * D_, M_);
        hgemm_kernel<2><<<gW1, 128, HG_SMEM>>>(h, w1 + (size_t)i * D_ * DFF_,
                                               b1 + i * DFF_, ff, M_, DFF_, D_);
        hgemm_kernel<1><<<gW2, 128, HG_SMEM>>>(ff, w2 + (size_t)i * DFF_ * D_,
                                               b2 + i * D_, x, M_, D_, DFF_);
    }

    {
        int warps = B_ * NVM_ + B_;
        out_kernel<<<(warps * 32 + 255) / 256, 256>>>(x, outW, outb, crW, crb, (float*)d_out);
    }
}

// round 16
// speedup vs baseline: 1.0677x; 1.0677x over previous
#include <cuda_runtime.h>
#include <cuda_fp16.h>
#include <cstdint>

// Problem constants
#define B_    4
#define NPM_  200
#define NVM_  1500
#define D_    512
#define H_    8
#define DFF_  2048
#define NL_   3
#define S_    1702           // NPM + NVM + 2
#define M_    (B_ * S_)      // 6808 rows
#define DH_   64
#define RELW_ (NPM_ + NVM_)  // 1700

// ----------------------------------------------------------------------------
// Scratch (static device globals; no allocation allowed)
// ----------------------------------------------------------------------------
__device__ float  g_x  [M_ * D_];       // residual stream (fp32)
__device__ __half g_h  [M_ * D_];       // layernorm output (GEMM A operand)
__device__ float  g_qkv[M_ * 3 * D_];   // qkv projection (fp32, attention reads)
__device__ __half g_o  [M_ * D_];       // attention output (GEMM A operand)
__device__ __half g_ff [M_ * DFF_];     // ffn hidden (GEMM A operand)
// transposed + fp16 weights, [N][K] per layer
__device__ __half g_wqkv[NL_ * D_ * 3 * D_];
__device__ __half g_wo  [NL_ * D_ * D_];
__device__ __half g_w1  [NL_ * D_ * DFF_];
__device__ __half g_w2  [NL_ * DFF_ * D_];
// attention sparsity structure
__device__ int g_sidx[B_ * RELW_];
__device__ int g_goff[B_ * (NPM_ + 1)];

// ----------------------------------------------------------------------------
// Setup mega-kernel: weight transpose+fp16, build_x, rel counting sort.
// ----------------------------------------------------------------------------
#define TILES_PER_LAYER 3072
#define PREP_BLOCKS (NL_ * TILES_PER_LAYER)                  // 9216
#define BX_BLOCKS   ((M_ * D_ + 255) / 256)                  // 13616
#define SETUP_BLOCKS (PREP_BLOCKS + BX_BLOCKS + B_)

__global__ void setup_kernel(const float* __restrict__ Wqkv, __half* __restrict__ wqkv,
                             const float* __restrict__ Wo,   __half* __restrict__ wo,
                             const float* __restrict__ W1,   __half* __restrict__ w1,
                             const float* __restrict__ W2,   __half* __restrict__ w2,
                             const float* __restrict__ vm,
                             const float* __restrict__ ns,
                             const float* __restrict__ pm,
                             const float* __restrict__ pmW, const float* __restrict__ pmb,
                             const float* __restrict__ vmW, const float* __restrict__ vmb,
                             float* __restrict__ x,
                             const int* __restrict__ rel, int* __restrict__ sidx,
                             int* __restrict__ goff)
{
    int bx = blockIdx.x;
    int tid = threadIdx.x;

    if (bx < PREP_BLOCKS) {
        __shared__ float t[32][33];
        int layer = bx / TILES_PER_LAYER;
        int tt = bx - layer * TILES_PER_LAYER;
        const float* W; __half* Wt; int K, N, t0;
        if (tt < 768)        { W = Wqkv + (size_t)layer * D_ * 3 * D_; Wt = wqkv + (size_t)layer * D_ * 3 * D_; K = D_;   N = 3 * D_; t0 = tt; }
        else if (tt < 1024)  { W = Wo   + (size_t)layer * D_ * D_;     Wt = wo   + (size_t)layer * D_ * D_;     K = D_;   N = D_;     t0 = tt - 768; }
        else if (tt < 2048)  { W = W1   + (size_t)layer * D_ * DFF_;   Wt = w1   + (size_t)layer * D_ * DFF_;   K = D_;   N = DFF_;   t0 = tt - 1024; }
        else                 { W = W2   + (size_t)layer * DFF_ * D_;   Wt = w2   + (size_t)layer * DFF_ * D_;   K = DFF_; N = D_;     t0 = tt - 2048; }
        int ntx = N >> 5;
        int n0 = (t0 % ntx) * 32;
        int k0 = (t0 / ntx) * 32;
        int tx = tid & 31, ty = tid >> 5;
        #pragma unroll
        for (int r = ty; r < 32; r += 8)
            t[r][tx] = W[(size_t)(k0 + r) * N + n0 + tx];
        __syncthreads();
        #pragma unroll
        for (int r = ty; r < 32; r += 8)
            Wt[(size_t)(n0 + r) * K + k0 + tx] = __float2half_rn(t[tx][r]);
    } else if (bx < PREP_BLOCKS + BX_BLOCKS) {
        int idx = (bx - PREP_BLOCKS) * 256 + tid;
        if (idx >= M_ * D_) return;
        int d = idx & (D_ - 1);
        int sb = idx >> 9;
        int s = sb % S_;
        int b = sb / S_;
        float val;
        if (s == 0) {
            val = ns[b];
        } else if (s <= NPM_) {
            const float* st = pm + ((size_t)b * NPM_ + (s - 1)) * 16;
            val = pmb[d];
            #pragma unroll
            for (int c = 0; c < 16; c++) val += st[c] * pmW[c * D_ + d];
        } else if (s < S_ - 1) {
            const float* st = vm + ((size_t)b * NVM_ + (s - 1 - NPM_)) * 16;
            val = vmb[d];
            #pragma unroll
            for (int c = 0; c < 16; c++) val += st[c] * vmW[c * D_ + d];
        } else {
            val = -1.0f;
        }
        x[idx] = val;
    } else {
        __shared__ int hist[NPM_];
        __shared__ int offs[NPM_ + 1];
        __shared__ int relv[RELW_];
        int b = bx - PREP_BLOCKS - BX_BLOCKS;
        for (int i = tid; i < NPM_; i += 256) hist[i] = 0;
        __syncthreads();
        for (int i = tid; i < RELW_; i += 256) {
            int r = rel[b * RELW_ + i];
            relv[i] = r;
            atomicAdd(&hist[r], 1);
        }
        __syncthreads();
        if (tid == 0) {
            int acc = 0;
            #pragma unroll 4
            for (int r = 0; r < NPM_; r++) {
                offs[r] = acc;
                goff[b * (NPM_ + 1) + r] = acc;
                acc += hist[r];
            }
            offs[NPM_] = acc;
            goff[b * (NPM_ + 1) + NPM_] = acc;
        }
        __syncthreads();
        int* out = sidx + b * RELW_;
        for (int r = tid; r < NPM_; r += 256) {
            int o = offs[r];
            for (int p = 0; p < RELW_; p++)
                if (relv[p] == r) out[o++] = p + 1;
        }
    }
}

// ----------------------------------------------------------------------------
// LayerNorm: one warp per row of 512; output fp16 (GEMM A operand)
// ----------------------------------------------------------------------------
__global__ void ln_kernel(const float* __restrict__ x, __half* __restrict__ out,
                          const float* __restrict__ gs, const float* __restrict__ gb,
                          int M)
{
    int warp = (blockIdx.x * blockDim.x + threadIdx.x) >> 5;
    int lane = threadIdx.x & 31;
    if (warp >= M) return;
    const float* row = x + (size_t)warp * D_;
    float4 v[4];
    float sum = 0.f, sq = 0.f;
    #pragma unroll
    for (int j = 0; j < 4; j++) {
        v[j] = *reinterpret_cast<const float4*>(row + (lane + 32 * j) * 4);
        sum += v[j].x + v[j].y + v[j].z + v[j].w;
        sq  += v[j].x * v[j].x + v[j].y * v[j].y + v[j].z * v[j].z + v[j].w * v[j].w;
    }
    #pragma unroll
    for (int o = 16; o; o >>= 1) {
        sum += __shfl_xor_sync(0xffffffffu, sum, o);
        sq  += __shfl_xor_sync(0xffffffffu, sq,  o);
    }
    const float inv = 1.0f / (float)D_;
    float mean = sum * inv;
    float var  = sq * inv - mean * mean;
    float rstd = rsqrtf(var + 1e-5f);
    __half* orow = out + (size_t)warp * D_;
    #pragma unroll
    for (int j = 0; j < 4; j++) {
        int c = (lane + 32 * j) * 4;
        __half2 lo = __floats2half2_rn((v[j].x - mean) * rstd * gs[c + 0] + gb[c + 0],
                                       (v[j].y - mean) * rstd * gs[c + 1] + gb[c + 1]);
        __half2 hi = __floats2half2_rn((v[j].z - mean) * rstd * gs[c + 2] + gb[c + 2],
                                       (v[j].w - mean) * rstd * gs[c + 3] + gb[c + 3]);
        *reinterpret_cast<__half2*>(orow + c)     = lo;
        *reinterpret_cast<__half2*>(orow + c + 2) = hi;
    }
}

// ----------------------------------------------------------------------------
// fp16 tensor-core GEMM (R11 config, best measured).
// ----------------------------------------------------------------------------
#define MMA_F16(d, a, b)                                                         \
    asm volatile(                                                                \
        "mma.sync.aligned.m16n8k16.row.col.f32.f16.f16.f32 "                     \
        "{%0,%1,%2,%3}, {%4,%5,%6,%7}, {%8,%9}, {%0,%1,%2,%3};"                  \
        : "+f"((d)[0]), "+f"((d)[1]), "+f"((d)[2]), "+f"((d)[3])                 \
        : "r"((a)[0]), "r"((a)[1]), "r"((a)[2]), "r"((a)[3]),                    \
          "r"((b)[0]), "r"((b)[1]))

#define LDSM4(r0, r1, r2, r3, addr)                                              \
    asm volatile("ldmatrix.sync.aligned.m8n8.x4.shared.b16 {%0,%1,%2,%3}, [%4];" \
        : "=r"(r0), "=r"(r1), "=r"(r2), "=r"(r3) : "r"(addr))

#define HG_STAGE_BYTES 20480
#define HG_SMEM (3 * HG_STAGE_BYTES)

template<int EPI>
__global__ void __launch_bounds__(128) hgemm_kernel(
    const __half* __restrict__ A, const __half* __restrict__ Wt,
    const float* __restrict__ bias, void* __restrict__ Cv,
    int M, int N, int K)
{
    extern __shared__ char sm_[];
    const uint32_t sbase = (uint32_t)__cvta_generic_to_shared(sm_);

    const int tid  = threadIdx.x;
    const int lane = tid & 31;
    const int wid  = tid >> 5;
    const int wm   = wid >> 1;
    const int wn   = wid & 1;
    const int g    = lane >> 2;
    const int c    = lane & 3;
    const int row0 = blockIdx.y * 128;
    const int col0 = blockIdx.x * 128;
    const int nk   = K >> 5;

    float acc[4][8][4];
    #pragma unroll
    for (int i = 0; i < 4; i++)
        #pragma unroll
        for (int j = 0; j < 8; j++)
            #pragma unroll
            for (int t = 0; t < 4; t++) acc[i][j][t] = 0.f;

    auto issue = [&](int kt, int st) {
        const int k0 = kt << 5;
        const uint32_t ab = sbase + st * HG_STAGE_BYTES;
        const uint32_t bb = ab + 10240;
        #pragma unroll
        for (int i = 0; i < 4; i++) {
            int idx = tid + i * 128;
            int r = idx >> 2, q = idx & 3;
            int m = row0 + r;
            const __half* src = A + (size_t)(m < M ? m : M - 1) * K + k0 + q * 8;
            uint32_t dst = ab + r * 80 + q * 16;
            int sz = (m < M) ? 16 : 0;
            asm volatile("cp.async.ca.shared.global [%0], [%1], 16, %2;"
                         :: "r"(dst), "l"(src), "r"(sz));
        }
        #pragma unroll
        for (int i = 0; i < 4; i++) {
            int idx = tid + i * 128;
            int r = idx >> 2, q = idx & 3;
            const __half* src = Wt + (size_t)(col0 + r) * K + k0 + q * 8;
            uint32_t dst = bb + r * 80 + q * 16;
            asm volatile("cp.async.cg.shared.global [%0], [%1], 16;"
                         :: "r"(dst), "l"(src));
        }
        asm volatile("cp.async.commit_group;");
    };

    const uint32_t rowA = (uint32_t)(lane & 15);
    const uint32_t colA = (uint32_t)((lane >> 4) * 8);
    const uint32_t rowB = (uint32_t)((lane & 7) + ((lane >> 4) * 8));
    const uint32_t colB = (uint32_t)(((lane >> 3) & 1) * 8);

    issue(0, 0);
    issue(1, 1);

    for (int kt = 0; kt < nk; kt++) {
        const int st = kt % 3;
        if (kt + 1 < nk) asm volatile("cp.async.wait_group 1;");
        else             asm volatile("cp.async.wait_group 0;");
        __syncthreads();
        if (kt + 2 < nk) issue(kt + 2, (kt + 2) % 3);

        const uint32_t ab = sbase + st * HG_STAGE_BYTES;
        const uint32_t bb = ab + 10240;

        #pragma unroll
        for (int ks = 0; ks < 2; ks++) {
            const uint32_t aoff = ab + (wm * 64 + rowA) * 80 + (colA + ks * 16) * 2;
            const uint32_t boff = bb + (wn * 64 + rowB) * 80 + (colB + ks * 16) * 2;
            uint32_t bf[8][2], af[4][4];
            #pragma unroll
            for (int p = 0; p < 4; p++) {
                LDSM4(bf[2 * p][0], bf[2 * p][1], bf[2 * p + 1][0], bf[2 * p + 1][1],
                      boff + p * 16 * 80);
            }
            #pragma unroll
            for (int fm = 0; fm < 4; fm++) {
                LDSM4(af[fm][0], af[fm][1], af[fm][2], af[fm][3],
                      aoff + fm * 16 * 80);
            }
            #pragma unroll
            for (int fm = 0; fm < 4; fm++)
                #pragma unroll
                for (int fn = 0; fn < 8; fn++)
                    MMA_F16(acc[fm][fn], af[fm], bf[fn]);
        }
        __syncthreads();
    }

    const int cc = c * 2;
    #pragma unroll
    for (int fm = 0; fm < 4; fm++) {
        int mA = row0 + wm * 64 + fm * 16 + g;
        int mB = mA + 8;
        #pragma unroll
        for (int fn = 0; fn < 8; fn++) {
            int n = col0 + wn * 64 + fn * 8 + cc;
            float2 b2 = *reinterpret_cast<const float2*>(bias + n);
            float v0 = acc[fm][fn][0] + b2.x;
            float v1 = acc[fm][fn][1] + b2.y;
            float v2 = acc[fm][fn][2] + b2.x;
            float v3 = acc[fm][fn][3] + b2.y;
            if (EPI == 0) {
                float* C = (float*)Cv;
                if (mA < M) *reinterpret_cast<float2*>(C + (size_t)mA * N + n) = make_float2(v0, v1);
                if (mB < M) *reinterpret_cast<float2*>(C + (size_t)mB * N + n) = make_float2(v2, v3);
            } else if (EPI == 1) {
                float* C = (float*)Cv;
                if (mA < M) {
                    float2* p = reinterpret_cast<float2*>(C + (size_t)mA * N + n);
                    float2 o = *p; o.x += v0; o.y += v1; *p = o;
                }
                if (mB < M) {
                    float2* p = reinterpret_cast<float2*>(C + (size_t)mB * N + n);
                    float2 o = *p; o.x += v2; o.y += v3; *p = o;
                }
            } else {
                __half* C = (__half*)Cv;
                float g0 = 0.5f * v0 * (1.0f + erff(v0 * 0.70710678118654752f));
                float g1 = 0.5f * v1 * (1.0f + erff(v1 * 0.70710678118654752f));
                float g2 = 0.5f * v2 * (1.0f + erff(v2 * 0.70710678118654752f));
                float g3 = 0.5f * v3 * (1.0f + erff(v3 * 0.70710678118654752f));
                if (mA < M) *reinterpret_cast<__half2*>(C + (size_t)mA * N + n) = __floats2half2_rn(g0, g1);
                if (mB < M) *reinterpret_cast<__half2*>(C + (size_t)mB * N + n) = __floats2half2_rn(g2, g3);
            }
        }
    }
}

// ----------------------------------------------------------------------------
// Fused attention: DENSE ROWS FIRST (blocks 0..63 — the serial long pole
// starts at t=0 and hides under the sparse phase), then sparse
// warp-per-(b,h,query) 2-key pairing (blocks 64..6863).
// ----------------------------------------------------------------------------
#define DENSE_BLOCKS (B_ * H_ * 2)           // 64
#define GRP_BLOCKS ((B_ * H_ * RELW_) / 8)   // 6800

__global__ void attn_kernel(const float* __restrict__ qkv,
                            const int* __restrict__ rel,
                            const int* __restrict__ sidx,
                            const int* __restrict__ goff,
                            const unsigned char* __restrict__ padm,
                            __half* __restrict__ obuf)
{
    __shared__ float sm[8], sl[8], so[8][64];
    const size_t rs = 3 * D_;
    int lane = threadIdx.x & 31;

    if (blockIdx.x >= DENSE_BLOCKS) {
        // ---- sparse: warp per (b, h, query), 2-key pairing ----
        int gw = (blockIdx.x - DENSE_BLOCKS) * 8 + (threadIdx.x >> 5);
        int qi = gw % RELW_;
        int bh = gw / RELW_;
        int h = bh % H_, b = bh / H_;
        int qpos = 1 + qi;

        const float* base = qkv + (size_t)b * S_ * rs + h * DH_;
        const float* qrow = base + (size_t)qpos * rs;
        float q0 = qrow[lane], q1 = qrow[lane + 32];

        int r   = rel[b * RELW_ + qi];
        int beg = goff[b * (NPM_ + 1) + r];
        int end = goff[b * (NPM_ + 1) + r + 1];
        const int* glist = sidx + b * RELW_;

        float m = -1e30f, l = 0.f, o0 = 0.f, o1 = 0.f;

        auto pair2 = [&](int k0p, int k1p) {
            const float* k0r = base + (size_t)k0p * rs + D_;
            const float* k1r = base + (size_t)k1p * rs + D_;
            const float* v0r = k0r + D_;
            const float* v1r = k1r + D_;
            float p0 = q0 * k0r[lane] + q1 * k0r[lane + 32];
            float p1 = q0 * k1r[lane] + q1 * k1r[lane + 32];
            float va0 = v0r[lane], va1 = v0r[lane + 32];
            float vb0 = v1r[lane], vb1 = v1r[lane + 32];
            #pragma unroll
            for (int o = 16; o; o >>= 1) {
                p0 += __shfl_xor_sync(0xffffffffu, p0, o);
                p1 += __shfl_xor_sync(0xffffffffu, p1, o);
            }
            float s0 = p0 * 0.125f, s1 = p1 * 0.125f;
            float mn = fmaxf(m, fmaxf(s0, s1));
            float corr = __expf(m - mn);
            float e0 = __expf(s0 - mn);
            float e1 = __expf(s1 - mn);
            o0 = o0 * corr + e0 * va0 + e1 * vb0;
            o1 = o1 * corr + e0 * va1 + e1 * vb1;
            l  = l * corr + e0 + e1;
            m  = mn;
        };
        auto single = [&](int kp) {
            const float* kr = base + (size_t)kp * rs + D_;
            const float* vr = kr + D_;
            float p = q0 * kr[lane] + q1 * kr[lane + 32];
            float v0 = vr[lane], v1 = vr[lane + 32];
            #pragma unroll
            for (int o = 16; o; o >>= 1) p += __shfl_xor_sync(0xffffffffu, p, o);
            float s = p * 0.125f;
            float mn = fmaxf(m, s);
            float corr = __expf(m - mn);
            float e = __expf(s - mn);
            o0 = o0 * corr + e * v0;
            o1 = o1 * corr + e * v1;
            l  = l * corr + e;
            m  = mn;
        };

        pair2(0, S_ - 1);
        int hold = -1;
        for (int i = beg; i < end; i++) {
            int kpos = glist[i];
            if (kpos > NPM_ && padm[b * NVM_ + kpos - 1 - NPM_]) continue;
            if (hold < 0) { hold = kpos; }
            else { pair2(hold, kpos); hold = -1; }
        }
        if (hold >= 0) single(hold);

        float inv = 1.0f / l;
        __half* dst = obuf + ((size_t)b * S_ + qpos) * D_ + h * DH_;
        dst[lane]      = __float2half_rn(o0 * inv);
        dst[lane + 32] = __float2half_rn(o1 * inv);
    } else {
        // ---- dense rows first: q in {0, S-1} ----
        int bx = blockIdx.x;
        int qsel = bx & 1;
        int h = (bx >> 1) & (H_ - 1);
        int b = bx >> 4;
        int qpos = qsel ? (S_ - 1) : 0;
        int warp = threadIdx.x >> 5;

        const float* base = qkv + (size_t)b * S_ * rs + h * DH_;
        const float* qrow = base + (size_t)qpos * rs;
        float q0 = qrow[lane], q1 = qrow[lane + 32];

        float m = -1e30f, l = 0.f, o0 = 0.f, o1 = 0.f;
        for (int k = warp; k < S_; k += 8) {
            if (k > NPM_ && k < S_ - 1 && padm[b * NVM_ + k - 1 - NPM_]) continue;
            const float* krow = base + (size_t)k * rs + D_;
            float p = q0 * krow[lane] + q1 * krow[lane + 32];
            #pragma unroll
            for (int o = 16; o; o >>= 1) p += __shfl_xor_sync(0xffffffffu, p, o);
            float s = p * 0.125f;
            float mn = fmaxf(m, s);
            float corr = __expf(m - mn);
            float pe   = __expf(s - mn);
            const float* vrow = krow + D_;
            o0 = o0 * corr + pe * vrow[lane];
            o1 = o1 * corr + pe * vrow[lane + 32];
            l  = l * corr + pe;
            m  = mn;
        }
        if (lane == 0) { sm[warp] = m; sl[warp] = l; }
        so[warp][lane]      = o0;
        so[warp][lane + 32] = o1;
        __syncthreads();

        if (threadIdx.x < 64) {
            float M = -1e30f;
            #pragma unroll
            for (int w = 0; w < 8; w++) M = fmaxf(M, sm[w]);
            float L = 0.f, ov = 0.f;
            #pragma unroll
            for (int w = 0; w < 8; w++) {
                float e = __expf(sm[w] - M);
                L  += sl[w] * e;
                ov += so[w][threadIdx.x] * e;
            }
            __half* dst = obuf + ((size_t)b * S_ + qpos) * D_ + h * DH_;
            dst[threadIdx.x] = __float2half_rn(ov / L);
        }
    }
}

// ----------------------------------------------------------------------------
// Output heads
// ----------------------------------------------------------------------------
__global__ void out_kernel(const float* __restrict__ x,
                           const float* __restrict__ outW, const float* __restrict__ outb,
                           const float* __restrict__ crW,  const float* __restrict__ crb,
                           float* __restrict__ out)
{
    int warp = (blockIdx.x * blockDim.x + threadIdx.x) >> 5;
    int lane = threadIdx.x & 31;
    const int nscore = B_ * NVM_;
    if (warp >= nscore + B_) return;
    int b, s;
    const float* w;
    float bias;
    float* dst;
    if (warp < nscore) {
        b = warp / NVM_;
        s = 1 + NPM_ + (warp % NVM_);
        w = outW; bias = outb[0];
        dst = out + warp;
    } else {
        b = warp - nscore;
        s = S_ - 1;
        w = crW; bias = crb[0];
        dst = out + nscore + b;
    }
    const float* row = x + ((size_t)b * S_ + s) * D_;
    float sum = 0.f;
    for (int c = lane; c < D_; c += 32) sum += row[c] * w[c];
    #pragma unroll
    for (int o = 16; o; o >>= 1) sum += __shfl_xor_sync(0xffffffffu, sum, o);
    if (lane == 0) *dst = sum + bias;
}

// ----------------------------------------------------------------------------
// Host launcher. Launch order: setup(0), ln(1), qkv(2), attn(3 <- PROFILED).
// ----------------------------------------------------------------------------
extern "C" void kernel_launch(void* const* d_in, const int* in_sizes, int n_in,
                              void* d_out, int out_size)
{
    const float* vm   = (const float*)d_in[0];
    const float* ns   = (const float*)d_in[1];
    const float* pm   = (const float*)d_in[2];
    const int*   rel  = (const int*)  d_in[3];
    const unsigned char* padm = (const unsigned char*)d_in[4];
    const float* pmW  = (const float*)d_in[5];
    const float* pmb  = (const float*)d_in[6];
    const float* vmW  = (const float*)d_in[7];
    const float* vmb  = (const float*)d_in[8];
    const float* ln1s = (const float*)d_in[9];
    const float* ln1b = (const float*)d_in[10];
    const float* Wqkv = (const float*)d_in[11];
    const float* bqkv = (const float*)d_in[12];
    const float* Wo   = (const float*)d_in[13];
    const float* bo   = (const float*)d_in[14];
    const float* ln2s = (const float*)d_in[15];
    const float* ln2b = (const float*)d_in[16];
    const float* W1   = (const float*)d_in[17];
    const float* b1   = (const float*)d_in[18];
    const float* W2   = (const float*)d_in[19];
    const float* b2   = (const float*)d_in[20];
    const float* outW = (const float*)d_in[21];
    const float* outb = (const float*)d_in[22];
    const float* crW  = (const float*)d_in[23];
    const float* crb  = (const float*)d_in[24];

    float *x, *qkvb;
    __half *h, *ob, *ff, *wqkv, *wo, *w1, *w2;
    int *sidx, *goff;
    cudaGetSymbolAddress((void**)&x,    g_x);
    cudaGetSymbolAddress((void**)&h,    g_h);
    cudaGetSymbolAddress((void**)&qkvb, g_qkv);
    cudaGetSymbolAddress((void**)&ob,   g_o);
    cudaGetSymbolAddress((void**)&ff,   g_ff);
    cudaGetSymbolAddress((void**)&wqkv, g_wqkv);
    cudaGetSymbolAddress((void**)&wo,   g_wo);
    cudaGetSymbolAddress((void**)&w1,   g_w1);
    cudaGetSymbolAddress((void**)&w2,   g_w2);
    cudaGetSymbolAddress((void**)&sidx, g_sidx);
    cudaGetSymbolAddress((void**)&goff, g_goff);

    cudaFuncSetAttribute(hgemm_kernel<0>, cudaFuncAttributeMaxDynamicSharedMemorySize, HG_SMEM);
    cudaFuncSetAttribute(hgemm_kernel<1>, cudaFuncAttributeMaxDynamicSharedMemorySize, HG_SMEM);
    cudaFuncSetAttribute(hgemm_kernel<2>, cudaFuncAttributeMaxDynamicSharedMemorySize, HG_SMEM);

    const int lnBlocks = (M_ * 32 + 255) / 256;
    const int MB = (M_ + 127) / 128;               // 54
    const dim3 gQKV(3 * D_ / 128, MB);             // (12, 54)
    const dim3 gWO (D_ / 128,     MB);             // (4, 54)
    const dim3 gW1 (DFF_ / 128,   MB);             // (16, 54)
    const dim3 gW2 (D_ / 128,     MB);             // (4, 54)
    const int attnBlocks = DENSE_BLOCKS + GRP_BLOCKS;  // 64 + 6800

    // launch 0: setup (weight prep + build_x + sort)
    setup_kernel<<<SETUP_BLOCKS, 256>>>(Wqkv, wqkv, Wo, wo, W1, w1, W2, w2,
                                        vm, ns, pm, pmW, pmb, vmW, vmb, x,
                                        rel, sidx, goff);
    // launch 1: LN1 (layer 0)
    ln_kernel<<<lnBlocks, 256>>>(x, h, ln1s, ln1b, M_);
    // launch 2: QKV GEMM (layer 0)
    hgemm_kernel<0><<<gQKV, 128, HG_SMEM>>>(h, wqkv, bqkv, qkvb, M_, 3 * D_, D_);

    for (int i = 0; i < NL_; i++) {
        if (i > 0) {
            ln_kernel<<<lnBlocks, 256>>>(x, h, ln1s + i * D_, ln1b + i * D_, M_);
            hgemm_kernel<0><<<gQKV, 128, HG_SMEM>>>(h, wqkv + (size_t)i * D_ * 3 * D_,
                                                    bqkv + i * 3 * D_, qkvb, M_, 3 * D_, D_);
        }
        // layer 0 attn is launch index 3 -> PROFILED
        attn_kernel<<<attnBlocks, 256>>>(qkvb, rel, sidx, goff, padm, ob);
        hgemm_kernel<1><<<gWO, 128, HG_SMEM>>>(ob, wo + (size_t)i * D_ * D_,
                                               bo + i * D_, x, M_, D_, D_);
        ln_kernel<<<lnBlocks, 256>>>(x, h, ln2s + i * D_, ln2b + i * D_, M_);
        hgemm_kernel<2><<<gW1, 128, HG_SMEM>>>(h, w1 + (size_t)i * D_ * DFF_,
                                               b1 + i * DFF_, ff, M_, DFF_, D_);
        hgemm_kernel<1><<<gW2, 128, HG_SMEM>>>(ff, w2 + (size_t)i * DFF_ * D_,
                                               b2 + i * D_, x, M_, D_, DFF_);
    }

    {
        int warps = B_ * NVM_ + B_;
        out_kernel<<<(warps * 32 + 255) / 256, 256>>>(x, outW, outb, crW, crb, (float*)d_out);
    }
}